// round 2
// baseline (speedup 1.0000x reference)
#include <cuda_runtime.h>
#include <cstdint>

#define B_   32
#define L_   256
#define T_   1600
#define C_   40
#define PADM 1.0e12f

// ---------------- scratch (__device__ globals; no allocation allowed) ----------------
__device__ __align__(16) float g_coefA[B_ * C_ * 2 * L_];   // invvar, duplicated pairs
__device__ __align__(16) float g_coefB[B_ * C_ * 2 * L_];   // mu*invvar, duplicated pairs
__device__ __align__(16) float g_t3 [B_ * L_];
__device__ __align__(16) float g_mlv[B_ * L_];

// ---------------- packed f32x2 helpers (sm_103a) ----------------
__device__ __forceinline__ unsigned long long pack2(float lo, float hi) {
    unsigned long long r;
    asm("mov.b64 %0, {%1,%2};" : "=l"(r) : "f"(lo), "f"(hi));
    return r;
}
#define FFMA2_ACC(d, a, b) \
    asm("fma.rn.f32x2 %0, %1, %2, %0;" : "+l"(d) : "l"(a), "l"(b))
#define FFMA2(d, a, b, c) \
    asm("fma.rn.f32x2 %0, %1, %2, %3;" : "=l"(d) : "l"(a), "l"(b), "l"(c))
#define ADD2(d, a, b) \
    asm("add.rn.f32x2 %0, %1, %2;" : "=l"(d) : "l"(a), "l"(b))

// ---------------- K0: per-(b,l) coefficients ----------------
__global__ void k0_coef(const float* __restrict__ mu_logvar) {
    int idx = blockIdx.x * 256 + threadIdx.x;          // 0 .. B*L-1
    int b = idx >> 8;
    int l = idx & (L_ - 1);
    const float* row = mu_logvar + (size_t)idx * (2 * C_);
    float* A  = g_coefA + (size_t)b * C_ * 2 * L_ + 2 * l;
    float* Bc = g_coefB + (size_t)b * C_ * 2 * L_ + 2 * l;
    float t3 = 0.f, slv = 0.f;
    for (int c = 0; c < C_; c++) {
        float mu = row[c];
        float lv = row[C_ + c];
        float iv = expf(-lv);
        float miv = mu * iv;
        A [c * 2 * L_]     = iv;
        A [c * 2 * L_ + 1] = iv;
        Bc[c * 2 * L_]     = miv;
        Bc[c * 2 * L_ + 1] = miv;
        t3 = fmaf(mu, miv, t3);
        slv += lv;
    }
    g_t3 [idx] = t3;
    g_mlv[idx] = slv * (1.0f / C_);
}

// ---------------- Kz: zero the alignment output region ----------------
__global__ void kz_zero(float4* __restrict__ p, int n4) {
    int i = blockIdx.x * blockDim.x + threadIdx.x;
    int stride = gridDim.x * blockDim.x;
    float4 z = make_float4(0.f, 0.f, 0.f, 0.f);
    for (; i < n4; i += stride) p[i] = z;
}

// ---------------- K1: lp[b][l][t] via packed FFMA2 GEMM ----------------
// block tile: 128 l x 64 t, 256 threads, each thread 4 l x 8 t
__global__ __launch_bounds__(256) void k1_lp(const float* __restrict__ z,
                                             float* __restrict__ lp_out) {
    __shared__ __align__(16) float zs [C_][64];
    __shared__ __align__(16) float z2s[C_][64];
    int b  = blockIdx.z;
    int l0 = blockIdx.y * 128;
    int t0 = blockIdx.x * 64;
    int tid = threadIdx.x;

    const float* zb = z + (size_t)b * C_ * T_ + t0;
    for (int i = tid; i < C_ * 64; i += 256) {
        int c = i >> 6, j = i & 63;
        float v = zb[(size_t)c * T_ + j];
        zs [c][j] = v;
        z2s[c][j] = v * v;
    }
    __syncthreads();

    int lg = tid >> 3, tg = tid & 7;
    int lbase = l0 + lg * 4;

    unsigned long long s1[4][4], s2[4][4];
#pragma unroll
    for (int r = 0; r < 4; r++)
#pragma unroll
        for (int j = 0; j < 4; j++) { s1[r][j] = 0ull; s2[r][j] = 0ull; }

    const float* cA = g_coefA + (size_t)b * C_ * 2 * L_ + 2 * lbase;
    const float* cB = g_coefB + (size_t)b * C_ * 2 * L_ + 2 * lbase;

#pragma unroll 2
    for (int c = 0; c < C_; c++) {
        ulonglong2 aL = *(const ulonglong2*)(cA + (size_t)c * 2 * L_);
        ulonglong2 aH = *(const ulonglong2*)(cA + (size_t)c * 2 * L_ + 4);
        ulonglong2 bL = *(const ulonglong2*)(cB + (size_t)c * 2 * L_);
        ulonglong2 bH = *(const ulonglong2*)(cB + (size_t)c * 2 * L_ + 4);
        unsigned long long ar[4] = {aL.x, aL.y, aH.x, aH.y};
        unsigned long long br[4] = {bL.x, bL.y, bH.x, bH.y};
        ulonglong2 q0 = *(const ulonglong2*)&z2s[c][tg * 8];
        ulonglong2 q1 = *(const ulonglong2*)&z2s[c][tg * 8 + 4];
        ulonglong2 w0 = *(const ulonglong2*)&zs [c][tg * 8];
        ulonglong2 w1 = *(const ulonglong2*)&zs [c][tg * 8 + 4];
        unsigned long long z2p[4] = {q0.x, q0.y, q1.x, q1.y};
        unsigned long long zp [4] = {w0.x, w0.y, w1.x, w1.y};
#pragma unroll
        for (int r = 0; r < 4; r++) {
#pragma unroll
            for (int j = 0; j < 4; j++) {
                FFMA2_ACC(s1[r][j], ar[r], z2p[j]);
                FFMA2_ACC(s2[r][j], br[r], zp[j]);
            }
        }
    }

    float4 t34 = *(const float4*)(g_t3  + b * L_ + lbase);
    float4 mv4 = *(const float4*)(g_mlv + b * L_ + lbase);
    float t3a[4] = {t34.x, t34.y, t34.z, t34.w};
    float mva[4] = {mv4.x, mv4.y, mv4.z, mv4.w};
    unsigned long long m2 = pack2(-2.0f, -2.0f);
    unsigned long long c1 = pack2(-0.0125f, -0.0125f);   // -0.5/C
#pragma unroll
    for (int r = 0; r < 4; r++) {
        unsigned long long tp = pack2(t3a[r], t3a[r]);
        unsigned long long dp = pack2(-0.5f * mva[r], -0.5f * mva[r]);
        unsigned long long o[4];
#pragma unroll
        for (int j = 0; j < 4; j++) {
            unsigned long long mse;
            FFMA2(mse, s2[r][j], m2, s1[r][j]);   // s1 - 2*s2
            ADD2(mse, mse, tp);                   // + t3
            FFMA2(o[j], mse, c1, dp);             // *(-1/80) + (-0.5*mlv)
        }
        float* orow = lp_out + ((size_t)b * L_ + lbase + r) * T_ + t0 + tg * 8;
        ((ulonglong2*)orow)[0] = make_ulonglong2(o[0], o[1]);
        ((ulonglong2*)orow)[1] = make_ulonglong2(o[2], o[3]);
    }
}

// ---------------- K2: forward DP (loss) + Viterbi (alignment) ----------------
// one block per batch; thread l = text position; smem: decision bits + ping-pong bufs
__global__ __launch_bounds__(256) void k2_dp(const float* __restrict__ lp,
                                             const int* __restrict__ tlen,
                                             const int* __restrict__ mlen,
                                             float* __restrict__ out_loss,
                                             float* __restrict__ out_align) {
    extern __shared__ unsigned char smraw[];
    unsigned* D   = (unsigned*)smraw;                    // [T_][8] ballot words
    float* abuf   = (float*)(smraw + (size_t)T_ * 8 * 4);// [2][256]
    float* bbuf   = abuf + 2 * L_;                       // [2][256]
    int*   path   = (int*)(bbuf + 2 * L_);               // [T_]
    float* shv    = (float*)(path + T_);

    int b  = blockIdx.x;
    int l  = threadIdx.x;
    int ml = mlen[b];
    int tl = tlen[b];

    const float* p = lp + ((size_t)b * L_ + l) * T_;

    float init = (l == 0) ? p[0] : -PADM;   // lp[b][0][0] only for l==0
    abuf[l] = init;
    bbuf[l] = init;
    __syncthreads();

    int pa = 0;
    float pf[4];
#pragma unroll
    for (int j = 0; j < 4; j++) pf[j] = p[1 + j];

    for (int t0 = 1; t0 < T_; t0 += 4) {
#pragma unroll
        for (int i = 0; i < 4; i++) {
            int t = t0 + i;
            if (t < T_) {
                int cur = pa << 8;
                int nxt = 256 - cur;
                float lpt = pf[i];
                float av  = abuf[cur + l];
                float avm = l ? abuf[cur + l - 1] : -PADM;
                float bv  = bbuf[cur + l];
                float bvm = l ? bbuf[cur + l - 1] : -PADM;
                // decision bits for column t-1 (beta_{t-1}), incl. wrap l=0 vs l=255
                float bw = bbuf[cur + ((l + 255) & 255)];
                unsigned bal = __ballot_sync(0xffffffffu, bw > bv);
                if ((l & 31) == 0) D[(t - 1) * 8 + (l >> 5)] = bal;
                // forward alpha: logaddexp(stay+eps, go+eps) + lp
                float s = av + 1e-7f, g = avm + 1e-7f;
                float m = fmaxf(s, g);
                float an = m + __logf(1.0f + __expf(-fabsf(s - g))) + lpt;
                // viterbi beta: max(stay, go) + lp
                float bn = fmaxf(bv, bvm) + lpt;
                abuf[nxt + l] = an;
                bbuf[nxt + l] = bn;
                if (t == ml - 1 && l == tl - 1) *shv = an;
                pa ^= 1;
                __syncthreads();
            }
            int tn = t0 + i + 4;
            pf[i] = (tn < T_) ? p[tn] : 0.0f;
        }
    }
    // bits for the last column (t = T-1)
    {
        int cur = pa << 8;
        float bv = bbuf[cur + l];
        float bw = bbuf[cur + ((l + 255) & 255)];
        unsigned bal = __ballot_sync(0xffffffffu, bw > bv);
        if ((l & 31) == 0) D[(T_ - 1) * 8 + (l >> 5)] = bal;
    }
    __syncthreads();

    // serial backtrack (exact emulation of reference relu/mod arithmetic)
    if (l == 0) {
        out_loss[b] = -(*shv) / (float)ml;
        int rows = tl - 1, cols = ml - 1;
        path[0] = rows;
        for (int k = 1; k < ml; k++) {
            int col = ((cols - 1) % T_ + T_) % T_;
            int br_ = rows & (L_ - 1);           // python mod for rows >= -1
            unsigned w = D[col * 8 + (br_ >> 5)];
            int is_go = (w >> (br_ & 31)) & 1;
            int tmp = rows - is_go + 1;
            rows = (tmp > 0 ? tmp : 0) - 1;
            cols = (cols > 0 ? cols : 0) - 1;
            path[k] = rows;
        }
    }
    __syncthreads();

    // write one-hot ones: final[t] = onehot(path[ml-1-t]) for t < ml
    size_t abase = (size_t)b * T_ * L_;
    for (int t = l; t < ml; t += 256) {
        int r = path[ml - 1 - t];
        if (r >= 0) out_align[abase + (size_t)t * L_ + r] = 1.0f;
    }
}

// ---------------- launch ----------------
extern "C" void kernel_launch(void* const* d_in, const int* in_sizes, int n_in,
                              void* d_out, int out_size) {
    const float* mu_logvar = (const float*)d_in[0];   // [B, L, 2C]
    const float* z         = (const float*)d_in[1];   // [B, C, T]
    const int*   tlen      = (const int*)d_in[2];     // [B]
    const int*   mlen      = (const int*)d_in[3];     // [B]

    float* out       = (float*)d_out;
    float* out_loss  = out;                                   // [B]
    float* out_align = out + B_;                              // [B, T, L]
    float* out_lp    = out_align + (size_t)B_ * T_ * L_;      // [B, L, T]

    size_t smem2 = (size_t)T_ * 8 * 4 + 2 * L_ * 4 + 2 * L_ * 4 + T_ * 4 + 16;
    cudaFuncSetAttribute(k2_dp, cudaFuncAttributeMaxDynamicSharedMemorySize,
                         (int)smem2);

    kz_zero<<<2048, 256>>>((float4*)out_align, (B_ * T_ * L_) / 4);
    k0_coef<<<B_, 256>>>(mu_logvar);
    dim3 g1(T_ / 64, L_ / 128, B_);
    k1_lp<<<g1, 256>>>(z, out_lp);
    k2_dp<<<B_, 256, smem2>>>(out_lp, tlen, mlen, out_loss, out_align);
}

// round 4
// speedup vs baseline: 1.0502x; 1.0502x over previous
#include <cuda_runtime.h>
#include <cstdint>

#define B_   32
#define L_   256
#define T_   1600
#define C_   40
#define PADM 1.0e12f

// ---------------- scratch (__device__ globals; no allocation allowed) ----------------
__device__ __align__(16) float g_coefA[B_ * C_ * 2 * L_];   // invvar, duplicated pairs
__device__ __align__(16) float g_coefB[B_ * C_ * 2 * L_];   // mu*invvar, duplicated pairs
__device__ __align__(16) float g_t3 [B_ * L_];
__device__ __align__(16) float g_mlv[B_ * L_];

// ---------------- packed f32x2 helpers (sm_103a) ----------------
__device__ __forceinline__ unsigned long long pack2(float lo, float hi) {
    unsigned long long r;
    asm("mov.b64 %0, {%1,%2};" : "=l"(r) : "f"(lo), "f"(hi));
    return r;
}
#define FFMA2_ACC(d, a, b) \
    asm("fma.rn.f32x2 %0, %1, %2, %0;" : "+l"(d) : "l"(a), "l"(b))
#define FFMA2(d, a, b, c) \
    asm("fma.rn.f32x2 %0, %1, %2, %3;" : "=l"(d) : "l"(a), "l"(b), "l"(c))
#define ADD2(d, a, b) \
    asm("add.rn.f32x2 %0, %1, %2;" : "=l"(d) : "l"(a), "l"(b))

// ---------------- K0: per-(b,l) coefficients ----------------
__global__ void k0_coef(const float* __restrict__ mu_logvar) {
    int idx = blockIdx.x * 256 + threadIdx.x;          // 0 .. B*L-1
    int b = idx >> 8;
    int l = idx & (L_ - 1);
    const float* row = mu_logvar + (size_t)idx * (2 * C_);
    float* A  = g_coefA + (size_t)b * C_ * 2 * L_ + 2 * l;
    float* Bc = g_coefB + (size_t)b * C_ * 2 * L_ + 2 * l;
    float t3 = 0.f, slv = 0.f;
    for (int c = 0; c < C_; c++) {
        float mu = row[c];
        float lv = row[C_ + c];
        float iv = expf(-lv);
        float miv = mu * iv;
        A [c * 2 * L_]     = iv;
        A [c * 2 * L_ + 1] = iv;
        Bc[c * 2 * L_]     = miv;
        Bc[c * 2 * L_ + 1] = miv;
        t3 = fmaf(mu, miv, t3);
        slv += lv;
    }
    g_t3 [idx] = t3;
    g_mlv[idx] = slv * (1.0f / C_);
}

// ---------------- Kz: zero the alignment output region ----------------
__global__ void kz_zero(float4* __restrict__ p, int n4) {
    int i = blockIdx.x * blockDim.x + threadIdx.x;
    int stride = gridDim.x * blockDim.x;
    float4 z = make_float4(0.f, 0.f, 0.f, 0.f);
    for (; i < n4; i += stride) p[i] = z;
}

// ---------------- K1: lp[b][l][t] via packed FFMA2 GEMM ----------------
// block tile: 128 l x 64 t, 256 threads, each thread 4 l x 8 t
__global__ __launch_bounds__(256) void k1_lp(const float* __restrict__ z,
                                             float* __restrict__ lp_out) {
    __shared__ __align__(16) float zs [C_][64];
    __shared__ __align__(16) float z2s[C_][64];
    int b  = blockIdx.z;
    int l0 = blockIdx.y * 128;
    int t0 = blockIdx.x * 64;
    int tid = threadIdx.x;

    const float* zb = z + (size_t)b * C_ * T_ + t0;
    for (int i = tid; i < C_ * 64; i += 256) {
        int c = i >> 6, j = i & 63;
        float v = zb[(size_t)c * T_ + j];
        zs [c][j] = v;
        z2s[c][j] = v * v;
    }
    __syncthreads();

    int lg = tid >> 3, tg = tid & 7;
    int lbase = l0 + lg * 4;

    unsigned long long s1[4][4], s2[4][4];
#pragma unroll
    for (int r = 0; r < 4; r++)
#pragma unroll
        for (int j = 0; j < 4; j++) { s1[r][j] = 0ull; s2[r][j] = 0ull; }

    const float* cA = g_coefA + (size_t)b * C_ * 2 * L_ + 2 * lbase;
    const float* cB = g_coefB + (size_t)b * C_ * 2 * L_ + 2 * lbase;

#pragma unroll 2
    for (int c = 0; c < C_; c++) {
        ulonglong2 aL = *(const ulonglong2*)(cA + (size_t)c * 2 * L_);
        ulonglong2 aH = *(const ulonglong2*)(cA + (size_t)c * 2 * L_ + 4);
        ulonglong2 bL = *(const ulonglong2*)(cB + (size_t)c * 2 * L_);
        ulonglong2 bH = *(const ulonglong2*)(cB + (size_t)c * 2 * L_ + 4);
        unsigned long long ar[4] = {aL.x, aL.y, aH.x, aH.y};
        unsigned long long br[4] = {bL.x, bL.y, bH.x, bH.y};
        ulonglong2 q0 = *(const ulonglong2*)&z2s[c][tg * 8];
        ulonglong2 q1 = *(const ulonglong2*)&z2s[c][tg * 8 + 4];
        ulonglong2 w0 = *(const ulonglong2*)&zs [c][tg * 8];
        ulonglong2 w1 = *(const ulonglong2*)&zs [c][tg * 8 + 4];
        unsigned long long z2p[4] = {q0.x, q0.y, q1.x, q1.y};
        unsigned long long zp [4] = {w0.x, w0.y, w1.x, w1.y};
#pragma unroll
        for (int r = 0; r < 4; r++) {
#pragma unroll
            for (int j = 0; j < 4; j++) {
                FFMA2_ACC(s1[r][j], ar[r], z2p[j]);
                FFMA2_ACC(s2[r][j], br[r], zp[j]);
            }
        }
    }

    float4 t34 = *(const float4*)(g_t3  + b * L_ + lbase);
    float4 mv4 = *(const float4*)(g_mlv + b * L_ + lbase);
    float t3a[4] = {t34.x, t34.y, t34.z, t34.w};
    float mva[4] = {mv4.x, mv4.y, mv4.z, mv4.w};
    unsigned long long m2 = pack2(-2.0f, -2.0f);
    unsigned long long c1 = pack2(-0.0125f, -0.0125f);   // -0.5/C
#pragma unroll
    for (int r = 0; r < 4; r++) {
        unsigned long long tp = pack2(t3a[r], t3a[r]);
        unsigned long long dp = pack2(-0.5f * mva[r], -0.5f * mva[r]);
        unsigned long long o[4];
#pragma unroll
        for (int j = 0; j < 4; j++) {
            unsigned long long mse;
            FFMA2(mse, s2[r][j], m2, s1[r][j]);   // s1 - 2*s2
            ADD2(mse, mse, tp);                   // + t3
            FFMA2(o[j], mse, c1, dp);             // *(-1/80) + (-0.5*mlv)
        }
        float* orow = lp_out + ((size_t)b * L_ + lbase + r) * T_ + t0 + tg * 8;
        ((ulonglong2*)orow)[0] = make_ulonglong2(o[0], o[1]);
        ((ulonglong2*)orow)[1] = make_ulonglong2(o[2], o[3]);
    }
}

// ---------------- K2: forward DP (loss) + Viterbi (alignment) ----------------
// one block per batch; thread l = text position; smem: decision bits + ping-pong bufs
__global__ __launch_bounds__(256) void k2_dp(const float* __restrict__ lp,
                                             const int* __restrict__ tlen,
                                             const int* __restrict__ mlen,
                                             float* __restrict__ out_loss,
                                             float* __restrict__ out_align) {
    extern __shared__ unsigned char smraw[];
    unsigned* D   = (unsigned*)smraw;                    // [T_][8] ballot words
    float* abuf   = (float*)(smraw + (size_t)T_ * 8 * 4);// [2][256]
    float* bbuf   = abuf + 2 * L_;                       // [2][256]
    int*   path   = (int*)(bbuf + 2 * L_);               // [T_]
    float* shv    = (float*)(path + T_);

    int b  = blockIdx.x;
    int l  = threadIdx.x;
    int ml = mlen[b];
    int tl = tlen[b];

    const float* p = lp + ((size_t)b * L_ + l) * T_;

    float init = (l == 0) ? p[0] : -PADM;   // lp[b][0][0] only for l==0
    abuf[l] = init;
    bbuf[l] = init;
    __syncthreads();

    int pa = 0;
    float pf[4];
#pragma unroll
    for (int j = 0; j < 4; j++) pf[j] = p[1 + j];

    for (int t0 = 1; t0 < T_; t0 += 4) {
#pragma unroll
        for (int i = 0; i < 4; i++) {
            int t = t0 + i;
            if (t < T_) {
                int cur = pa << 8;
                int nxt = 256 - cur;
                float lpt = pf[i];
                float av  = abuf[cur + l];
                float avm = l ? abuf[cur + l - 1] : -PADM;
                float bv  = bbuf[cur + l];
                float bvm = l ? bbuf[cur + l - 1] : -PADM;
                // decision bits for column t-1 (beta_{t-1}), incl. wrap l=0 vs l=255
                float bw = bbuf[cur + ((l + 255) & 255)];
                unsigned bal = __ballot_sync(0xffffffffu, bw > bv);
                if ((l & 31) == 0) D[(t - 1) * 8 + (l >> 5)] = bal;
                // forward alpha: logaddexp(stay+eps, go+eps) + lp
                float s = av + 1e-7f, g = avm + 1e-7f;
                float m = fmaxf(s, g);
                float an = m + __logf(1.0f + __expf(-fabsf(s - g))) + lpt;
                // viterbi beta: max(stay, go) + lp
                float bn = fmaxf(bv, bvm) + lpt;
                abuf[nxt + l] = an;
                bbuf[nxt + l] = bn;
                if (t == ml - 1 && l == tl - 1) *shv = an;
                pa ^= 1;
                __syncthreads();
            }
            int tn = t0 + i + 4;
            pf[i] = (tn < T_) ? p[tn] : 0.0f;
        }
    }
    // bits for the last column (t = T-1)
    {
        int cur = pa << 8;
        float bv = bbuf[cur + l];
        float bw = bbuf[cur + ((l + 255) & 255)];
        unsigned bal = __ballot_sync(0xffffffffu, bw > bv);
        if ((l & 31) == 0) D[(T_ - 1) * 8 + (l >> 5)] = bal;
    }
    __syncthreads();

    // serial backtrack (exact emulation of reference relu/mod arithmetic)
    if (l == 0) {
        out_loss[b] = -(*shv) / (float)ml;
        int rows = tl - 1, cols = ml - 1;
        path[0] = rows;
        for (int k = 1; k < ml; k++) {
            int col = ((cols - 1) % T_ + T_) % T_;
            int br_ = rows & (L_ - 1);           // python mod for rows >= -1
            unsigned w = D[col * 8 + (br_ >> 5)];
            int is_go = (w >> (br_ & 31)) & 1;
            int tmp = rows - is_go + 1;
            rows = (tmp > 0 ? tmp : 0) - 1;
            cols = (cols > 0 ? cols : 0) - 1;
            path[k] = rows;
        }
    }
    __syncthreads();

    // write one-hot ones: final[t] = onehot(path[ml-1-t]) for t < ml
    size_t abase = (size_t)b * T_ * L_;
    for (int t = l; t < ml; t += 256) {
        int r = path[ml - 1 - t];
        if (r >= 0) out_align[abase + (size_t)t * L_ + r] = 1.0f;
    }
}

// ---------------- launch ----------------
extern "C" void kernel_launch(void* const* d_in, const int* in_sizes, int n_in,
                              void* d_out, int out_size) {
    const float* mu_logvar = (const float*)d_in[0];   // [B, L, 2C]
    const float* z         = (const float*)d_in[1];   // [B, C, T]
    const int*   tlen      = (const int*)d_in[2];     // [B]
    const int*   mlen      = (const int*)d_in[3];     // [B]

    float* out       = (float*)d_out;
    float* out_loss  = out;                                   // [B]
    float* out_align = out + B_;                              // [B, T, L]
    float* out_lp    = out_align + (size_t)B_ * T_ * L_;      // [B, L, T]

    size_t smem2 = (size_t)T_ * 8 * 4 + 2 * L_ * 4 + 2 * L_ * 4 + T_ * 4 + 16;
    cudaFuncSetAttribute(k2_dp, cudaFuncAttributeMaxDynamicSharedMemorySize,
                         (int)smem2);

    kz_zero<<<2048, 256>>>((float4*)out_align, (B_ * T_ * L_) / 4);
    k0_coef<<<B_, 256>>>(mu_logvar);
    dim3 g1(T_ / 64, L_ / 128, B_);
    k1_lp<<<g1, 256>>>(z, out_lp);
    k2_dp<<<B_, 256, smem2>>>(out_lp, tlen, mlen, out_loss, out_align);
}

// round 6
// speedup vs baseline: 1.4502x; 1.3809x over previous
#include <cuda_runtime.h>
#include <cstdint>

#define B_   32
#define L_   256
#define T_   1600
#define C_   40
#define PADM 1.0e12f

// ---------------- scratch (__device__ globals; no allocation allowed) ----------------
__device__ __align__(16) float g_coefA[B_ * C_ * 2 * L_];   // invvar, duplicated pairs
__device__ __align__(16) float g_coefB[B_ * C_ * 2 * L_];   // mu*invvar, duplicated pairs
__device__ __align__(16) float g_t3 [B_ * L_];
__device__ __align__(16) float g_mlv[B_ * L_];

// ---------------- packed f32x2 helpers (sm_103a) ----------------
__device__ __forceinline__ unsigned long long pack2(float lo, float hi) {
    unsigned long long r;
    asm("mov.b64 %0, {%1,%2};" : "=l"(r) : "f"(lo), "f"(hi));
    return r;
}
#define FFMA2_ACC(d, a, b) \
    asm("fma.rn.f32x2 %0, %1, %2, %0;" : "+l"(d) : "l"(a), "l"(b))
#define FFMA2(d, a, b, c) \
    asm("fma.rn.f32x2 %0, %1, %2, %3;" : "=l"(d) : "l"(a), "l"(b), "l"(c))
#define ADD2(d, a, b) \
    asm("add.rn.f32x2 %0, %1, %2;" : "=l"(d) : "l"(a), "l"(b))

// volatile 128-bit shared ld/st (single-instruction mailbox access)
__device__ __forceinline__ uint4 ldsv4v(unsigned a) {
    uint4 r;
    asm volatile("ld.volatile.shared.v4.b32 {%0,%1,%2,%3},[%4];"
                 : "=r"(r.x), "=r"(r.y), "=r"(r.z), "=r"(r.w) : "r"(a));
    return r;
}
__device__ __forceinline__ void stsv4v(unsigned a, uint4 v) {
    asm volatile("st.volatile.shared.v4.b32 [%0],{%1,%2,%3,%4};"
                 :: "r"(a), "r"(v.x), "r"(v.y), "r"(v.z), "r"(v.w));
}

// ---------------- K0: per-(b,l) coefficients ----------------
__global__ void k0_coef(const float* __restrict__ mu_logvar) {
    int idx = blockIdx.x * 256 + threadIdx.x;          // 0 .. B*L-1
    int b = idx >> 8;
    int l = idx & (L_ - 1);
    const float* row = mu_logvar + (size_t)idx * (2 * C_);
    float* A  = g_coefA + (size_t)b * C_ * 2 * L_ + 2 * l;
    float* Bc = g_coefB + (size_t)b * C_ * 2 * L_ + 2 * l;
    float t3 = 0.f, slv = 0.f;
    for (int c = 0; c < C_; c++) {
        float mu = row[c];
        float lv = row[C_ + c];
        float iv = expf(-lv);
        float miv = mu * iv;
        A [c * 2 * L_]     = iv;
        A [c * 2 * L_ + 1] = iv;
        Bc[c * 2 * L_]     = miv;
        Bc[c * 2 * L_ + 1] = miv;
        t3 = fmaf(mu, miv, t3);
        slv += lv;
    }
    g_t3 [idx] = t3;
    g_mlv[idx] = slv * (1.0f / C_);
}

// ---------------- Kz: zero the alignment output region ----------------
__global__ void kz_zero(float4* __restrict__ p, int n4) {
    int i = blockIdx.x * blockDim.x + threadIdx.x;
    int stride = gridDim.x * blockDim.x;
    float4 z = make_float4(0.f, 0.f, 0.f, 0.f);
    for (; i < n4; i += stride) p[i] = z;
}

// ---------------- K1: lp[b][l][t] via packed FFMA2 GEMM ----------------
// block tile: 128 l x 64 t, 256 threads, each thread 4 l x 8 t
__global__ __launch_bounds__(256) void k1_lp(const float* __restrict__ z,
                                             float* __restrict__ lp_out) {
    __shared__ __align__(16) float zs [C_][64];
    __shared__ __align__(16) float z2s[C_][64];
    int b  = blockIdx.z;
    int l0 = blockIdx.y * 128;
    int t0 = blockIdx.x * 64;
    int tid = threadIdx.x;

    const float* zb = z + (size_t)b * C_ * T_ + t0;
    for (int i = tid; i < C_ * 64; i += 256) {
        int c = i >> 6, j = i & 63;
        float v = zb[(size_t)c * T_ + j];
        zs [c][j] = v;
        z2s[c][j] = v * v;
    }
    __syncthreads();

    int lg = tid >> 3, tg = tid & 7;
    int lbase = l0 + lg * 4;

    unsigned long long s1[4][4], s2[4][4];
#pragma unroll
    for (int r = 0; r < 4; r++)
#pragma unroll
        for (int j = 0; j < 4; j++) { s1[r][j] = 0ull; s2[r][j] = 0ull; }

    const float* cA = g_coefA + (size_t)b * C_ * 2 * L_ + 2 * lbase;
    const float* cB = g_coefB + (size_t)b * C_ * 2 * L_ + 2 * lbase;

#pragma unroll 2
    for (int c = 0; c < C_; c++) {
        ulonglong2 aL = *(const ulonglong2*)(cA + (size_t)c * 2 * L_);
        ulonglong2 aH = *(const ulonglong2*)(cA + (size_t)c * 2 * L_ + 4);
        ulonglong2 bL = *(const ulonglong2*)(cB + (size_t)c * 2 * L_);
        ulonglong2 bH = *(const ulonglong2*)(cB + (size_t)c * 2 * L_ + 4);
        unsigned long long ar[4] = {aL.x, aL.y, aH.x, aH.y};
        unsigned long long br[4] = {bL.x, bL.y, bH.x, bH.y};
        ulonglong2 q0 = *(const ulonglong2*)&z2s[c][tg * 8];
        ulonglong2 q1 = *(const ulonglong2*)&z2s[c][tg * 8 + 4];
        ulonglong2 w0 = *(const ulonglong2*)&zs [c][tg * 8];
        ulonglong2 w1 = *(const ulonglong2*)&zs [c][tg * 8 + 4];
        unsigned long long z2p[4] = {q0.x, q0.y, q1.x, q1.y};
        unsigned long long zp [4] = {w0.x, w0.y, w1.x, w1.y};
#pragma unroll
        for (int r = 0; r < 4; r++) {
#pragma unroll
            for (int j = 0; j < 4; j++) {
                FFMA2_ACC(s1[r][j], ar[r], z2p[j]);
                FFMA2_ACC(s2[r][j], br[r], zp[j]);
            }
        }
    }

    float4 t34 = *(const float4*)(g_t3  + b * L_ + lbase);
    float4 mv4 = *(const float4*)(g_mlv + b * L_ + lbase);
    float t3a[4] = {t34.x, t34.y, t34.z, t34.w};
    float mva[4] = {mv4.x, mv4.y, mv4.z, mv4.w};
    unsigned long long m2 = pack2(-2.0f, -2.0f);
    unsigned long long c1 = pack2(-0.0125f, -0.0125f);   // -0.5/C
#pragma unroll
    for (int r = 0; r < 4; r++) {
        unsigned long long tp = pack2(t3a[r], t3a[r]);
        unsigned long long dp = pack2(-0.5f * mva[r], -0.5f * mva[r]);
        unsigned long long o[4];
#pragma unroll
        for (int j = 0; j < 4; j++) {
            unsigned long long mse;
            FFMA2(mse, s2[r][j], m2, s1[r][j]);   // s1 - 2*s2
            ADD2(mse, mse, tp);                   // + t3
            FFMA2(o[j], mse, c1, dp);             // *(-1/80) + (-0.5*mlv)
        }
        float* orow = lp_out + ((size_t)b * L_ + lbase + r) * T_ + t0 + tg * 8;
        ((ulonglong2*)orow)[0] = make_ulonglong2(o[0], o[1]);
        ((ulonglong2*)orow)[1] = make_ulonglong2(o[2], o[3]);
    }
}

// ---------------- K2: barrier-free forward DP + Viterbi ----------------
// one block per batch; thread l = text position; alpha/beta in registers;
// shfl_up for intra-warp l-1; tagged smem mailbox ring for warp boundaries.
// smem layout (dynamic):
//   [0, 51200)        D: decision ballot words [T_][8]
//   [51200, 55296)    mailbox: 8 warps x 32 slots x 16B {tag, alpha, beta, pad}
//   [55296, 61696)    path[T_]
//   [61696, 61700)    shv (alpha at (tl-1, ml-1))
#define SM2_MB   51200
#define SM2_PATH 55296
#define SM2_SHV  61696
#define SM2_TOT  61712

__global__ __launch_bounds__(256, 1) void k2_dp(const float* __restrict__ lp,
                                                const int* __restrict__ tlen,
                                                const int* __restrict__ mlen,
                                                float* __restrict__ out_loss,
                                                float* __restrict__ out_align) {
    extern __shared__ unsigned char smraw[];
    unsigned* D = (unsigned*)smraw;
    int* path   = (int*)(smraw + SM2_PATH);
    float* shv  = (float*)(smraw + SM2_SHV);
    unsigned smbase = (unsigned)__cvta_generic_to_shared(smraw);
    unsigned mbbase = smbase + SM2_MB;

    int b = blockIdx.x;
    int l = threadIdx.x;
    int w = l >> 5, lane = l & 31;
    int ml = mlen[b], tl = tlen[b];
    const float* p = lp + ((size_t)b * L_ + l) * T_;

    unsigned mb_self = mbbase + (unsigned)w * 512u;
    unsigned mb_src  = mbbase + (unsigned)((w + 7) & 7) * 512u;  // warp w-1 (warp0 -> warp7)

    float4 vcur = *(const float4*)p;           // lp[t=0..3]
    float a  = (l == 0) ? vcur.x : -PADM;      // alpha(t=0)
    float bt = a;                              // beta(t=0)

    // publish init slot (lane31 values at t=0 are all -PADM)
    if (lane == 31)
        stsv4v(mb_self, make_uint4(0u, __float_as_uint(-PADM), __float_as_uint(-PADM), 0u));
    __syncthreads();   // make init slots + tag space visible (only barrier before loop)

    float4 vnext = *(const float4*)(p + 4);

    for (int k = 0; k < T_ / 4; k++) {
        float4 vpref = vcur;
        if (k + 2 < T_ / 4) vpref = *(const float4*)(p + 4 * (k + 2));
        float lt[4] = {vcur.x, vcur.y, vcur.z, vcur.w};
#pragma unroll
        for (int j = 0; j < 4; j++) {
            int t = 4 * k + j;
            if (t == 0) continue;
            // poll producer boundary slot for step t-1
            unsigned tag = (unsigned)(t - 1);
            unsigned saddr = mb_src + (tag & 31u) * 16u;
            uint4 s = ldsv4v(saddr);
            while (s.x != tag) s = ldsv4v(saddr);
            float mba = __uint_as_float(s.y);
            float mbb = __uint_as_float(s.z);
            // neighbor values at t-1
            float sa = __shfl_up_sync(0xffffffffu, a, 1);
            float sb = __shfl_up_sync(0xffffffffu, bt, 1);
            float am, bm, bw;
            if (lane == 0) {
                bw = mbb;                         // ballot wrap: beta[l-1 mod 256]
                if (w == 0) { am = -PADM; bm = -PADM; }
                else        { am = mba;   bm = mbb; }
            } else { am = sa; bm = sb; bw = sb; }
            // decision bits for column t-1 (beta values at t-1)
            unsigned bal = __ballot_sync(0xffffffffu, bw > bt);
            if (lane == 0) D[(t - 1) * 8 + w] = bal;
            // recurrences
            float lpv = lt[j];
            float d  = a - am;
            float m  = fmaxf(a, am);
            float sp = __logf(1.0f + __expf(-fabsf(d)));
            float an = m + sp + (lpv + 1e-7f);       // logaddexp(a+eps,am+eps)+lp
            float bn = fmaxf(bt, bm) + lpv;
            if (t == ml - 1 && l == tl - 1) *shv = an;
            if (lane == 31)
                stsv4v(mb_self + ((unsigned)t & 31u) * 16u,
                       make_uint4((unsigned)t, __float_as_uint(an), __float_as_uint(bn), 0u));
            a = an; bt = bn;
        }
        vcur = vnext; vnext = vpref;
    }

    // decision bits for the last column (t = T-1)
    {
        unsigned tag = (unsigned)(T_ - 1);
        unsigned saddr = mb_src + (tag & 31u) * 16u;
        uint4 s = ldsv4v(saddr);
        while (s.x != tag) s = ldsv4v(saddr);
        float sb = __shfl_up_sync(0xffffffffu, bt, 1);
        float bw = (lane == 0) ? __uint_as_float(s.z) : sb;
        unsigned bal = __ballot_sync(0xffffffffu, bw > bt);
        if (lane == 0) D[(T_ - 1) * 8 + w] = bal;
    }
    __syncthreads();

    // serial backtrack with group-of-8 word prefetch
    if (l == 0) {
        out_loss[b] = -(*shv) / (float)ml;
        int rows = tl - 1;
        path[0] = rows;
        int k = 1;
        for (; k + 7 <= ml - 1; k += 8) {
            int colbase = ml - 1 - k;            // cols colbase .. colbase-7, all >= 0
            int w0 = (rows & 255) >> 5;
            int w1 = (w0 + 7) & 7;
            unsigned Wa[8], Wb[8];
#pragma unroll
            for (int d2 = 0; d2 < 8; d2++) {
                Wa[d2] = D[(colbase - d2) * 8 + w0];
                Wb[d2] = D[(colbase - d2) * 8 + w1];
            }
#pragma unroll
            for (int d2 = 0; d2 < 8; d2++) {
                int br = rows & 255;
                unsigned word = ((br >> 5) == w0) ? Wa[d2] : Wb[d2];
                int is_go = (word >> (br & 31)) & 1;
                int tmp = rows - is_go + 1;
                rows = (tmp > 0 ? tmp : 0) - 1;
                path[k + d2] = rows;
            }
        }
        for (; k <= ml - 1; k++) {
            int col = ml - 1 - k;
            int br = rows & 255;
            unsigned word = D[col * 8 + (br >> 5)];
            int is_go = (word >> (br & 31)) & 1;
            int tmp = rows - is_go + 1;
            rows = (tmp > 0 ? tmp : 0) - 1;
            path[k] = rows;
        }
    }
    __syncthreads();

    // write one-hot ones: final[t] = onehot(path[ml-1-t]) for t < ml
    size_t abase = (size_t)b * T_ * L_;
    for (int t = l; t < ml; t += 256) {
        int r = path[ml - 1 - t];
        if (r >= 0) out_align[abase + (size_t)t * L_ + r] = 1.0f;
    }
}

// ---------------- launch ----------------
extern "C" void kernel_launch(void* const* d_in, const int* in_sizes, int n_in,
                              void* d_out, int out_size) {
    const float* mu_logvar = (const float*)d_in[0];   // [B, L, 2C]
    const float* z         = (const float*)d_in[1];   // [B, C, T]
    const int*   tlen      = (const int*)d_in[2];     // [B]
    const int*   mlen      = (const int*)d_in[3];     // [B]

    float* out       = (float*)d_out;
    float* out_loss  = out;                                   // [B]
    float* out_align = out + B_;                              // [B, T, L]
    float* out_lp    = out_align + (size_t)B_ * T_ * L_;      // [B, L, T]

    cudaFuncSetAttribute(k2_dp, cudaFuncAttributeMaxDynamicSharedMemorySize,
                         SM2_TOT);

    kz_zero<<<2048, 256>>>((float4*)out_align, (B_ * T_ * L_) / 4);
    k0_coef<<<B_, 256>>>(mu_logvar);
    dim3 g1(T_ / 64, L_ / 128, B_);
    k1_lp<<<g1, 256>>>(z, out_lp);
    k2_dp<<<B_, 256, SM2_TOT>>>(out_lp, tlen, mlen, out_loss, out_align);
}